// round 2
// baseline (speedup 1.0000x reference)
#include <cuda_runtime.h>
#include <math.h>

#define NE      8
#define HIDDEN  2048
#define INTER   4096
#define TOKENS  8192
#define SLOTS   (TOKENS * 2)
#define SLOTS_PAD 16896          // 16384 + 8*64 worst-case tile padding
#define BM 64
#define BN 64
#define BK 16
#define MTILES (SLOTS_PAD / BM)  // 264

// ---------------- scratch (device globals: allocation-free) ----------------
__device__ int   g_topk_idx[SLOTS];
__device__ float g_topk_w[SLOTS];
__device__ int   g_counts[NE];
__device__ int   g_off[NE + 1];
__device__ int   g_tok[SLOTS_PAD];
__device__ float g_coef[SLOTS_PAD];
__device__ float g_h[(size_t)SLOTS_PAD * INTER];   // ~277 MB

// ---------------- router: logits -> softmax -> top2 ----------------
__global__ __launch_bounds__(256) void router_kernel(const float* __restrict__ x,
                                                     const float* __restrict__ gw) {
    __shared__ float xs[HIDDEN];
    __shared__ float logits[NE];
    int t   = blockIdx.x;
    int tid = threadIdx.x;
    const float* xr = x + (size_t)t * HIDDEN;
    for (int i = tid; i < HIDDEN; i += 256) xs[i] = xr[i];
    __syncthreads();
    int w = tid >> 5, lane = tid & 31;   // 8 warps = 8 experts
    const float* gr = gw + (size_t)w * HIDDEN;
    float s = 0.f;
    for (int i = lane; i < HIDDEN; i += 32) s += xs[i] * gr[i];
    #pragma unroll
    for (int o = 16; o; o >>= 1) s += __shfl_xor_sync(0xffffffffu, s, o);
    if (lane == 0) logits[w] = s;
    __syncthreads();
    if (tid == 0) {
        float m = logits[0];
        #pragma unroll
        for (int e = 1; e < NE; e++) m = fmaxf(m, logits[e]);
        float p[NE]; float sum = 0.f;
        #pragma unroll
        for (int e = 0; e < NE; e++) { p[e] = __expf(logits[e] - m); sum += p[e]; }
        float inv = 1.f / sum;
        #pragma unroll
        for (int e = 0; e < NE; e++) p[e] *= inv;
        int i1 = 0;
        #pragma unroll
        for (int e = 1; e < NE; e++) if (p[e] > p[i1]) i1 = e;   // lowest index on tie
        int i2 = (i1 == 0) ? 1 : 0;
        #pragma unroll
        for (int e = 0; e < NE; e++) if (e != i1 && e != i2 && p[e] > p[i2]) i2 = e;
        g_topk_idx[2 * t]     = i1;  g_topk_w[2 * t]     = p[i1];
        g_topk_idx[2 * t + 1] = i2;  g_topk_w[2 * t + 1] = p[i2];
    }
}

__global__ void zero_counts_kernel() {
    if (threadIdx.x < NE) g_counts[threadIdx.x] = 0;
}

__global__ void count_kernel() {
    int i = blockIdx.x * blockDim.x + threadIdx.x;
    if (i < SLOTS) atomicAdd(&g_counts[g_topk_idx[i]], 1);
}

__global__ void offsets_kernel() {
    if (threadIdx.x == 0) {
        int o = 0;
        for (int e = 0; e < NE; e++) {
            g_off[e] = o;
            o += ((g_counts[e] + BM - 1) / BM) * BM;   // pad segment to tile
        }
        g_off[NE] = o;
    }
}

// deterministic, token-ordered scatter into per-expert segments
__global__ __launch_bounds__(256) void build_lists_kernel() {
    int e = blockIdx.x;
    int tid = threadIdx.x, lane = tid & 31, wid = tid >> 5;
    __shared__ int wsum[8];
    __shared__ int sbase;
    if (tid == 0) sbase = g_off[e];
    __syncthreads();
    for (int base = 0; base < TOKENS; base += 256) {
        int t = base + tid;
        int match = 0; float c = 0.f;
        int i0 = g_topk_idx[2 * t], i1 = g_topk_idx[2 * t + 1];
        if (i0 == e)      { match = 1; c = g_topk_w[2 * t]; }
        else if (i1 == e) { match = 1; c = g_topk_w[2 * t + 1]; }
        unsigned m = __ballot_sync(0xffffffffu, match);
        if (lane == 0) wsum[wid] = __popc(m);
        __syncthreads();
        int woff = 0, tot = 0;
        #pragma unroll
        for (int i = 0; i < 8; i++) { int v = wsum[i]; if (i < wid) woff += v; tot += v; }
        if (match) {
            int p = sbase + woff + __popc(m & ((1u << lane) - 1));
            g_tok[p] = t; g_coef[p] = c;
        }
        __syncthreads();
        if (tid == 0) sbase += tot;
        __syncthreads();
    }
    // zero-fill tile padding
    int end = g_off[e + 1];
    for (int p = g_off[e] + g_counts[e] + tid; p < end; p += 256) {
        g_tok[p] = 0; g_coef[p] = 0.f;
    }
}

// ---------------- GEMM1: h = silu(x@w1^T) * (x@w3^T), gathered rows ----------------
__global__ __launch_bounds__(256, 2) void gemm1_kernel(const float* __restrict__ x,
                                                       const float* __restrict__ w1,
                                                       const float* __restrict__ w3) {
    __shared__ float As [BK][BM + 4];
    __shared__ float B1s[BK][BN + 4];
    __shared__ float B3s[BK][BN + 4];
    __shared__ int rtok[BM];

    int r0 = blockIdx.y * BM;
    if (r0 >= g_off[NE]) return;
    int e = 0;
    #pragma unroll
    for (int i = 1; i < NE; i++) if (r0 >= g_off[i]) e = i;
    int n0 = blockIdx.x * BN;
    int tid = threadIdx.x;
    if (tid < BM) rtok[tid] = g_tok[r0 + tid];
    __syncthreads();

    int lrow = tid >> 2, lk = (tid & 3) << 2;   // loader: 4 threads/row, float4 each
    int tx = tid & 15, ty = tid >> 4;           // 16x16 threads, 4x4 microtile

    const float* arow  = x  + (size_t)rtok[lrow] * HIDDEN + lk;
    const float* b1row = w1 + ((size_t)e * INTER + n0 + lrow) * HIDDEN + lk;
    const float* b3row = w3 + ((size_t)e * INTER + n0 + lrow) * HIDDEN + lk;

    float accg[4][4] = {}, accu[4][4] = {};

    for (int k0 = 0; k0 < HIDDEN; k0 += BK) {
        float4 av  = *(const float4*)(arow  + k0);
        float4 b1v = *(const float4*)(b1row + k0);
        float4 b3v = *(const float4*)(b3row + k0);
        __syncthreads();
        As [lk+0][lrow] = av.x;  As [lk+1][lrow] = av.y;  As [lk+2][lrow] = av.z;  As [lk+3][lrow] = av.w;
        B1s[lk+0][lrow] = b1v.x; B1s[lk+1][lrow] = b1v.y; B1s[lk+2][lrow] = b1v.z; B1s[lk+3][lrow] = b1v.w;
        B3s[lk+0][lrow] = b3v.x; B3s[lk+1][lrow] = b3v.y; B3s[lk+2][lrow] = b3v.z; B3s[lk+3][lrow] = b3v.w;
        __syncthreads();
        #pragma unroll
        for (int kk = 0; kk < BK; kk++) {
            float4 a  = *(const float4*)(&As [kk][ty << 2]);
            float4 b1 = *(const float4*)(&B1s[kk][tx << 2]);
            float4 b3 = *(const float4*)(&B3s[kk][tx << 2]);
            float ar[4] = {a.x, a.y, a.z, a.w};
            float b1r[4] = {b1.x, b1.y, b1.z, b1.w};
            float b3r[4] = {b3.x, b3.y, b3.z, b3.w};
            #pragma unroll
            for (int i = 0; i < 4; i++)
                #pragma unroll
                for (int j = 0; j < 4; j++) {
                    accg[i][j] = fmaf(ar[i], b1r[j], accg[i][j]);
                    accu[i][j] = fmaf(ar[i], b3r[j], accu[i][j]);
                }
        }
    }

    #pragma unroll
    for (int i = 0; i < 4; i++) {
        int r = r0 + (ty << 2) + i;
        float res[4];
        #pragma unroll
        for (int j = 0; j < 4; j++) {
            float g = accg[i][j], u = accu[i][j];
            float s = g / (1.f + __expf(-g));   // silu
            res[j] = s * u;
        }
        *(float4*)(&g_h[(size_t)r * INTER + n0 + (tx << 2)]) =
            make_float4(res[0], res[1], res[2], res[3]);
    }
}

// ---------------- GEMM2: out[tok] += coef * (h @ w2^T) ----------------
__global__ __launch_bounds__(256, 2) void gemm2_kernel(const float* __restrict__ w2,
                                                       float* __restrict__ out) {
    __shared__ float As[BK][BM + 4];
    __shared__ float Bs[BK][BN + 4];
    __shared__ int   rtok[BM];
    __shared__ float rcoef[BM];

    int r0 = blockIdx.y * BM;
    if (r0 >= g_off[NE]) return;
    int e = 0;
    #pragma unroll
    for (int i = 1; i < NE; i++) if (r0 >= g_off[i]) e = i;
    int n0 = blockIdx.x * BN;
    int tid = threadIdx.x;
    if (tid < BM) { rtok[tid] = g_tok[r0 + tid]; rcoef[tid] = g_coef[r0 + tid]; }
    __syncthreads();

    int lrow = tid >> 2, lk = (tid & 3) << 2;
    int tx = tid & 15, ty = tid >> 4;

    const float* arow = g_h + (size_t)(r0 + lrow) * INTER + lk;
    const float* brow = w2  + ((size_t)e * HIDDEN + n0 + lrow) * INTER + lk;

    float acc[4][4] = {};

    for (int k0 = 0; k0 < INTER; k0 += BK) {
        float4 av = *(const float4*)(arow + k0);
        float4 bv = *(const float4*)(brow + k0);
        __syncthreads();
        As[lk+0][lrow] = av.x; As[lk+1][lrow] = av.y; As[lk+2][lrow] = av.z; As[lk+3][lrow] = av.w;
        Bs[lk+0][lrow] = bv.x; Bs[lk+1][lrow] = bv.y; Bs[lk+2][lrow] = bv.z; Bs[lk+3][lrow] = bv.w;
        __syncthreads();
        #pragma unroll
        for (int kk = 0; kk < BK; kk++) {
            float4 a = *(const float4*)(&As[kk][ty << 2]);
            float4 b = *(const float4*)(&Bs[kk][tx << 2]);
            float ar[4] = {a.x, a.y, a.z, a.w};
            float br[4] = {b.x, b.y, b.z, b.w};
            #pragma unroll
            for (int i = 0; i < 4; i++)
                #pragma unroll
                for (int j = 0; j < 4; j++)
                    acc[i][j] = fmaf(ar[i], br[j], acc[i][j]);
        }
    }

    #pragma unroll
    for (int i = 0; i < 4; i++) {
        int rl = (ty << 2) + i;
        float c = rcoef[rl];
        if (c != 0.f) {
            float* base = out + (size_t)rtok[rl] * HIDDEN + n0 + (tx << 2);
            #pragma unroll
            for (int j = 0; j < 4; j++) atomicAdd(base + j, c * acc[i][j]);
        }
    }
}

// ---------------- launch ----------------
extern "C" void kernel_launch(void* const* d_in, const int* in_sizes, int n_in,
                              void* d_out, int out_size) {
    const float* x  = (const float*)d_in[0];
    const float* gw = (const float*)d_in[1];
    const float* w1 = (const float*)d_in[2];
    const float* w2 = (const float*)d_in[3];
    const float* w3 = (const float*)d_in[4];
    float* out = (float*)d_out;

    cudaMemsetAsync(d_out, 0, (size_t)TOKENS * HIDDEN * sizeof(float), 0);
    zero_counts_kernel<<<1, 32>>>();
    router_kernel<<<TOKENS, 256>>>(x, gw);
    count_kernel<<<SLOTS / 256, 256>>>();
    offsets_kernel<<<1, 1>>>();
    build_lists_kernel<<<NE, 256>>>();
    gemm1_kernel<<<dim3(INTER / BN, MTILES), 256>>>(x, w1, w3);
    gemm2_kernel<<<dim3(HIDDEN / BN, MTILES), 256>>>(w2, out);
}

// round 7
// speedup vs baseline: 2.9111x; 2.9111x over previous
#include <cuda_runtime.h>
#include <cstdint>
#include <math.h>

#define NE      8
#define HIDDEN  2048
#define INTER   4096
#define TOKENS  8192
#define SLOTS   (TOKENS * 2)
#define PADM    128
#define SLOTS_PAD (SLOTS + NE * PADM)   // 17408
#define MT      (SLOTS_PAD / PADM)      // 136
#define KC      32                      // K elems per pipeline chunk

// ---------------- scratch (device globals: allocation-free, ~285 MB total) ----------------
__device__ int   g_topk_idx[SLOTS];
__device__ float g_topk_w[SLOTS];
__device__ int   g_counts[NE];
__device__ int   g_off[NE + 1];
__device__ int   g_tok[SLOTS_PAD];
__device__ float g_coef[SLOTS_PAD];
__device__ float g_h[(size_t)SLOTS_PAD * INTER];   // ~285 MB

// ---------------- helpers ----------------
__device__ __forceinline__ uint32_t swz(uint32_t off) { return off ^ ((off >> 3) & 0x70); }

__device__ __forceinline__ float rna_tf32(float f) {
    uint32_t r;
    asm("cvt.rna.tf32.f32 %0, %1;" : "=r"(r) : "f"(f));
    return __uint_as_float(r);
}
__device__ __forceinline__ uint4 tf32x4(float4 v) {
    uint4 r;
    asm("cvt.rna.tf32.f32 %0, %1;" : "=r"(r.x) : "f"(v.x));
    asm("cvt.rna.tf32.f32 %0, %1;" : "=r"(r.y) : "f"(v.y));
    asm("cvt.rna.tf32.f32 %0, %1;" : "=r"(r.z) : "f"(v.z));
    asm("cvt.rna.tf32.f32 %0, %1;" : "=r"(r.w) : "f"(v.w));
    return r;
}
__device__ __forceinline__ uint4 as_u4(float4 v) { return *(uint4*)&v; }

// m16n8k8 tf32 mma: D/C fp32, A row-major, B col-major
__device__ __forceinline__ void mma8(float* c, const uint32_t* a, uint32_t b0, uint32_t b1) {
    asm volatile(
        "mma.sync.aligned.m16n8k8.row.col.f32.tf32.tf32.f32 "
        "{%0,%1,%2,%3},{%4,%5,%6,%7},{%8,%9},{%0,%1,%2,%3};"
        : "+f"(c[0]), "+f"(c[1]), "+f"(c[2]), "+f"(c[3])
        : "r"(a[0]), "r"(a[1]), "r"(a[2]), "r"(a[3]), "r"(b0), "r"(b1));
}

// ---------------- router ----------------
__global__ __launch_bounds__(256) void router_kernel(const float* __restrict__ x,
                                                     const float* __restrict__ gw) {
    __shared__ float xs[HIDDEN];
    __shared__ float logits[NE];
    int t = blockIdx.x, tid = threadIdx.x;
    const float* xr = x + (size_t)t * HIDDEN;
    for (int i = tid; i < HIDDEN; i += 256) xs[i] = xr[i];
    __syncthreads();
    int w = tid >> 5, lane = tid & 31;
    const float* gr = gw + (size_t)w * HIDDEN;
    float s = 0.f;
    for (int i = lane; i < HIDDEN; i += 32) s += xs[i] * gr[i];
    #pragma unroll
    for (int o = 16; o; o >>= 1) s += __shfl_xor_sync(0xffffffffu, s, o);
    if (lane == 0) logits[w] = s;
    __syncthreads();
    if (tid == 0) {
        float m = logits[0];
        #pragma unroll
        for (int e = 1; e < NE; e++) m = fmaxf(m, logits[e]);
        float p[NE]; float sum = 0.f;
        #pragma unroll
        for (int e = 0; e < NE; e++) { p[e] = __expf(logits[e] - m); sum += p[e]; }
        float inv = 1.f / sum;
        #pragma unroll
        for (int e = 0; e < NE; e++) p[e] *= inv;
        int i1 = 0;
        #pragma unroll
        for (int e = 1; e < NE; e++) if (p[e] > p[i1]) i1 = e;
        int i2 = (i1 == 0) ? 1 : 0;
        #pragma unroll
        for (int e = 0; e < NE; e++) if (e != i1 && e != i2 && p[e] > p[i2]) i2 = e;
        g_topk_idx[2 * t] = i1;     g_topk_w[2 * t] = p[i1];
        g_topk_idx[2 * t + 1] = i2; g_topk_w[2 * t + 1] = p[i2];
    }
}

__global__ void zero_counts_kernel() { if (threadIdx.x < NE) g_counts[threadIdx.x] = 0; }
__global__ void count_kernel() {
    int i = blockIdx.x * blockDim.x + threadIdx.x;
    if (i < SLOTS) atomicAdd(&g_counts[g_topk_idx[i]], 1);
}
__global__ void offsets_kernel() {
    if (threadIdx.x == 0) {
        int o = 0;
        for (int e = 0; e < NE; e++) { g_off[e] = o; o += ((g_counts[e] + PADM - 1) / PADM) * PADM; }
        g_off[NE] = o;
    }
}
__global__ __launch_bounds__(256) void build_lists_kernel() {
    int e = blockIdx.x, tid = threadIdx.x, lane = tid & 31, wid = tid >> 5;
    __shared__ int wsum[8]; __shared__ int sbase;
    if (tid == 0) sbase = g_off[e];
    __syncthreads();
    for (int base = 0; base < TOKENS; base += 256) {
        int t = base + tid; int match = 0; float c = 0.f;
        int i0 = g_topk_idx[2 * t], i1 = g_topk_idx[2 * t + 1];
        if (i0 == e) { match = 1; c = g_topk_w[2 * t]; }
        else if (i1 == e) { match = 1; c = g_topk_w[2 * t + 1]; }
        unsigned m = __ballot_sync(0xffffffffu, match);
        if (lane == 0) wsum[wid] = __popc(m);
        __syncthreads();
        int woff = 0, tot = 0;
        #pragma unroll
        for (int i = 0; i < 8; i++) { int v = wsum[i]; if (i < wid) woff += v; tot += v; }
        if (match) { int p = sbase + woff + __popc(m & ((1u << lane) - 1)); g_tok[p] = t; g_coef[p] = c; }
        __syncthreads();
        if (tid == 0) sbase += tot;
        __syncthreads();
    }
    int end = g_off[e + 1];
    for (int p = g_off[e] + g_counts[e] + tid; p < end; p += 256) { g_tok[p] = 0; g_coef[p] = 0.f; }
}

// ---------------- GEMM1: g_h = silu(x@w1^T) * (x@w3^T) ----------------
// CTA tile: M=128, N=64 (each of g,u), K-chunk=32. 2-stage LDG->cvt->STS pipeline.
// stage layout: A[128x32] @0 (16KB), B1[64x32] @16384 (8KB), B3[64x32] @24576 (8KB)
#define G1_STAGE  32768
#define G1_SMEMSZ (2 * G1_STAGE + 512)

__global__ __launch_bounds__(256) void gemm1_kernel(const float* __restrict__ x,
                                                    const float* __restrict__ w1,
                                                    const float* __restrict__ w3) {
    extern __shared__ char sm[];
    const int r0 = blockIdx.y * PADM;
    if (r0 >= g_off[NE]) return;
    int e = 0;
    #pragma unroll
    for (int i = 1; i < NE; i++) if (r0 >= g_off[i]) e = i;
    const int n0 = blockIdx.x * 64;
    const int tid = threadIdx.x, wid = tid >> 5, lane = tid & 31;
    int* rtok = (int*)(sm + 2 * G1_STAGE);
    if (tid < 128) rtok[tid] = g_tok[r0 + tid];
    __syncthreads();

    // loader mapping: 8 x 16B chunks per 128B row; thread -> (row=tid>>3 + 32j, chunk=tid&7)
    const int lr = tid >> 3, lc = tid & 7;
    const float* ag[4]; uint32_t asA[4];
    #pragma unroll
    for (int j = 0; j < 4; j++) {
        int row = lr + 32 * j;
        ag[j]  = x + (size_t)rtok[row] * HIDDEN + lc * 4;
        asA[j] = swz(row * 128 + lc * 16);
    }
    const float* b1g[2]; const float* b3g[2]; uint32_t asB[2];
    #pragma unroll
    for (int j = 0; j < 2; j++) {
        int row = lr + 32 * j;
        b1g[j] = w1 + ((size_t)e * INTER + n0 + row) * HIDDEN + lc * 4;
        b3g[j] = w3 + ((size_t)e * INTER + n0 + row) * HIDDEN + lc * 4;
        asB[j] = swz(row * 128 + lc * 16);
    }

    float4 pA[4], pB1[2], pB3[2];
    auto prefetch = [&](int kc) {
        int k0 = kc * KC;
        #pragma unroll
        for (int j = 0; j < 4; j++) pA[j]  = __ldg((const float4*)(ag[j] + k0));
        #pragma unroll
        for (int j = 0; j < 2; j++) pB1[j] = __ldg((const float4*)(b1g[j] + k0));
        #pragma unroll
        for (int j = 0; j < 2; j++) pB3[j] = __ldg((const float4*)(b3g[j] + k0));
    };
    auto stage_store = [&](int st) {
        char* base = sm + st * G1_STAGE;
        #pragma unroll
        for (int j = 0; j < 4; j++) *(uint4*)(base + asA[j])         = tf32x4(pA[j]);
        #pragma unroll
        for (int j = 0; j < 2; j++) *(uint4*)(base + 16384 + asB[j]) = tf32x4(pB1[j]);
        #pragma unroll
        for (int j = 0; j < 2; j++) *(uint4*)(base + 24576 + asB[j]) = tf32x4(pB3[j]);
    };

    const int mw = wid & 1, nw = wid >> 1;       // 2 x 4 warp grid; warp = 64M x 16N
    const int r = lane >> 2, q = lane & 3;
    float accg[4][2][4] = {}, accu[4][2][4] = {};

    prefetch(0);
    const int NCk = HIDDEN / KC;   // 64
    for (int kc = 0; kc < NCk; kc++) {
        int st = kc & 1;
        __syncthreads();              // buf st consumed by compute(kc-2)
        stage_store(st);
        __syncthreads();
        if (kc + 1 < NCk) prefetch(kc + 1);   // LDG latency hidden by compute below
        const char* A  = sm + st * G1_STAGE;
        const char* B1 = A + 16384;
        const char* B3 = A + 24576;
        #pragma unroll
        for (int k8 = 0; k8 < 4; k8++) {
            uint32_t a[4][4];
            const int col = (k8 * 8 + q) * 4;
            #pragma unroll
            for (int i = 0; i < 4; i++) {
                int row = mw * 64 + i * 16 + r;
                a[i][0] = *(const uint32_t*)(A + swz(row * 128 + col));
                a[i][1] = *(const uint32_t*)(A + swz((row + 8) * 128 + col));
                a[i][2] = *(const uint32_t*)(A + swz(row * 128 + col + 16));
                a[i][3] = *(const uint32_t*)(A + swz((row + 8) * 128 + col + 16));
            }
            #pragma unroll
            for (int j = 0; j < 2; j++) {
                int nr = nw * 16 + j * 8 + r;
                uint32_t b1a = *(const uint32_t*)(B1 + swz(nr * 128 + col));
                uint32_t b1b = *(const uint32_t*)(B1 + swz(nr * 128 + col + 16));
                uint32_t b3a = *(const uint32_t*)(B3 + swz(nr * 128 + col));
                uint32_t b3b = *(const uint32_t*)(B3 + swz(nr * 128 + col + 16));
                #pragma unroll
                for (int i = 0; i < 4; i++) {
                    mma8(accg[i][j], a[i], b1a, b1b);
                    mma8(accu[i][j], a[i], b3a, b3b);
                }
            }
        }
    }

    // epilogue: h = rna(silu(g) * u), stored tf32-rounded for gemm2
    #pragma unroll
    for (int i = 0; i < 4; i++) {
        int row0 = r0 + mw * 64 + i * 16 + r;
        #pragma unroll
        for (int j = 0; j < 2; j++) {
            int cg = n0 + nw * 16 + j * 8 + q * 2;
            float g0 = accg[i][j][0], g1 = accg[i][j][1], g2 = accg[i][j][2], g3 = accg[i][j][3];
            float u0 = accu[i][j][0], u1 = accu[i][j][1], u2 = accu[i][j][2], u3 = accu[i][j][3];
            float h0 = rna_tf32((g0 / (1.f + __expf(-g0))) * u0);
            float h1 = rna_tf32((g1 / (1.f + __expf(-g1))) * u1);
            float h2 = rna_tf32((g2 / (1.f + __expf(-g2))) * u2);
            float h3 = rna_tf32((g3 / (1.f + __expf(-g3))) * u3);
            *(float2*)(g_h + (size_t)row0 * INTER + cg)       = make_float2(h0, h1);
            *(float2*)(g_h + (size_t)(row0 + 8) * INTER + cg) = make_float2(h2, h3);
        }
    }
}

// ---------------- GEMM2: out[tok] += coef * (h @ w2^T) ----------------
// CTA tile: M=128, N=128, K-chunk=32. stage: A[128x32] @0, B[128x32] @16384
#define G2_STAGE  32768
#define G2_SMEMSZ (2 * G2_STAGE + 1024)

__global__ __launch_bounds__(256) void gemm2_kernel(const float* __restrict__ w2,
                                                    float* __restrict__ out) {
    extern __shared__ char sm[];
    const int r0 = blockIdx.y * PADM;
    if (r0 >= g_off[NE]) return;
    int e = 0;
    #pragma unroll
    for (int i = 1; i < NE; i++) if (r0 >= g_off[i]) e = i;
    const int n0 = blockIdx.x * 128;
    const int tid = threadIdx.x, wid = tid >> 5, lane = tid & 31;
    int*   rtok  = (int*)(sm + 2 * G2_STAGE);
    float* rcoef = (float*)(sm + 2 * G2_STAGE + 512);
    if (tid < 128) { rtok[tid] = g_tok[r0 + tid]; rcoef[tid] = g_coef[r0 + tid]; }
    __syncthreads();

    const int lr = tid >> 3, lc = tid & 7;
    const float* ag[4]; const float* bg[4]; uint32_t asT[4];
    #pragma unroll
    for (int j = 0; j < 4; j++) {
        int row = lr + 32 * j;
        ag[j]  = g_h + (size_t)(r0 + row) * INTER + lc * 4;
        bg[j]  = w2  + ((size_t)e * HIDDEN + n0 + row) * INTER + lc * 4;
        asT[j] = swz(row * 128 + lc * 16);
    }

    float4 pA[4], pB[4];
    auto prefetch = [&](int kc) {
        int k0 = kc * KC;
        #pragma unroll
        for (int j = 0; j < 4; j++) pA[j] = __ldg((const float4*)(ag[j] + k0));
        #pragma unroll
        for (int j = 0; j < 4; j++) pB[j] = __ldg((const float4*)(bg[j] + k0));
    };
    auto stage_store = [&](int st) {
        char* base = sm + st * G2_STAGE;
        #pragma unroll
        for (int j = 0; j < 4; j++) *(uint4*)(base + asT[j])         = as_u4(pA[j]);  // g_h pre-rounded
        #pragma unroll
        for (int j = 0; j < 4; j++) *(uint4*)(base + 16384 + asT[j]) = tf32x4(pB[j]);
    };

    const int mw = wid & 1, nw = wid >> 1;       // warp = 64M x 32N
    const int r = lane >> 2, q = lane & 3;
    float acc[4][4][4] = {};

    prefetch(0);
    const int NCk = INTER / KC;   // 128
    for (int kc = 0; kc < NCk; kc++) {
        int st = kc & 1;
        __syncthreads();
        stage_store(st);
        __syncthreads();
        if (kc + 1 < NCk) prefetch(kc + 1);
        const char* A = sm + st * G2_STAGE;
        const char* B = A + 16384;
        #pragma unroll
        for (int k8 = 0; k8 < 4; k8++) {
            uint32_t a[4][4];
            const int col = (k8 * 8 + q) * 4;
            #pragma unroll
            for (int i = 0; i < 4; i++) {
                int row = mw * 64 + i * 16 + r;
                a[i][0] = *(const uint32_t*)(A + swz(row * 128 + col));
                a[i][1] = *(const uint32_t*)(A + swz((row + 8) * 128 + col));
                a[i][2] = *(const uint32_t*)(A + swz(row * 128 + col + 16));
                a[i][3] = *(const uint32_t*)(A + swz((row + 8) * 128 + col + 16));
            }
            #pragma unroll
            for (int j = 0; j < 4; j++) {
                int nr = nw * 32 + j * 8 + r;
                uint32_t b0 = *(const uint32_t*)(B + swz(nr * 128 + col));
                uint32_t b1 = *(const uint32_t*)(B + swz(nr * 128 + col + 16));
                #pragma unroll
                for (int i = 0; i < 4; i++) mma8(acc[i][j], a[i], b0, b1);
            }
        }
    }

    // epilogue: atomic scatter with routing coefficient
    #pragma unroll
    for (int i = 0; i < 4; i++) {
        int rl = mw * 64 + i * 16 + r;
        float cf0 = rcoef[rl], cf1 = rcoef[rl + 8];
        int   tk0 = rtok[rl],  tk1 = rtok[rl + 8];
        #pragma unroll
        for (int j = 0; j < 4; j++) {
            int cg = n0 + nw * 32 + j * 8 + q * 2;
            if (cf0 != 0.f) {
                float* p = out + (size_t)tk0 * HIDDEN + cg;
                atomicAdd(p,     cf0 * acc[i][j][0]);
                atomicAdd(p + 1, cf0 * acc[i][j][1]);
            }
            if (cf1 != 0.f) {
                float* p = out + (size_t)tk1 * HIDDEN + cg;
                atomicAdd(p,     cf1 * acc[i][j][2]);
                atomicAdd(p + 1, cf1 * acc[i][j][3]);
            }
        }
    }
}

// ---------------- launch ----------------
extern "C" void kernel_launch(void* const* d_in, const int* in_sizes, int n_in,
                              void* d_out, int out_size) {
    const float* x  = (const float*)d_in[0];
    const float* gw = (const float*)d_in[1];
    const float* w1 = (const float*)d_in[2];
    const float* w2 = (const float*)d_in[3];
    const float* w3 = (const float*)d_in[4];
    float* out = (float*)d_out;

    cudaFuncSetAttribute(gemm1_kernel, cudaFuncAttributeMaxDynamicSharedMemorySize, G1_SMEMSZ);
    cudaFuncSetAttribute(gemm2_kernel, cudaFuncAttributeMaxDynamicSharedMemorySize, G2_SMEMSZ);

    cudaMemsetAsync(d_out, 0, (size_t)TOKENS * HIDDEN * sizeof(float), 0);

    zero_counts_kernel<<<1, 32>>>();
    router_kernel<<<TOKENS, 256>>>(x, gw);
    count_kernel<<<SLOTS / 256, 256>>>();
    offsets_kernel<<<1, 1>>>();
    build_lists_kernel<<<NE, 256>>>();

    gemm1_kernel<<<dim3(INTER / 64, MT), 256, G1_SMEMSZ>>>(x, w1, w3);
    gemm2_kernel<<<dim3(HIDDEN / 128, MT), 256, G2_SMEMSZ>>>(w2, out);
}